// round 14
// baseline (speedup 1.0000x reference)
#include <cuda_runtime.h>
#include <cstdint>
#include <math.h>

#define NEXP   4096
#define NPTS   65536
#define NRAYS  1024
#define HID    32
#define IN_PTS 63
#define IN_DIR 27
#define MAXO   14336
#define GRID_MLP 296
#define PREP_BLOCKS (NPTS / 64)    // 1024
#define DIR_BLOCKS  (NRAYS / 64)   // 16

typedef unsigned long long ull;

// ---- scratch (no allocations allowed) ----
__device__ int    g_counts[NEXP];
__device__ int    g_offsets[NEXP];       // point offsets, multiples of 8
__device__ int    g_expert[NPTS];
__device__ int    g_rank[NPTS];
__device__ int    g_flag;
__device__ int    g_O;                   // total octs
__device__ int    g_oexp[MAXO];          // oct -> expert
__device__ int    g_olist[MAXO * 8];     // padded point list (-1 = pad)
__device__ float4 g_xp4[NPTS * 16];      // AXIS-MAJOR xp rows (63 pad 64)
__device__ float4 g_xd4[NRAYS * 8];      // AXIS-MAJOR xd rows (27 pad 32)

// axis-major slot -> original feature row (compile-time after unroll)
__device__ __forceinline__ constexpr int oxp(int s) {
    int a = s / 21, r = s % 21;
    return (r == 0) ? a : ((r & 1) ? (3 + 6 * ((r - 1) / 2) + a)
                                   : (6 + 6 * ((r - 2) / 2) + a));
}
__device__ __forceinline__ constexpr int oxd(int s) {
    int a = s / 9, r = s % 9;
    return (r == 0) ? a : ((r & 1) ? (3 + 6 * ((r - 1) / 2) + a)
                                   : (6 + 6 * ((r - 2) / 2) + a));
}

// ---- f32x2 packed helpers ----
__device__ __forceinline__ ull pk(float a, float b) {
    ull r; asm("mov.b64 %0, {%1,%2};" : "=l"(r) : "f"(a), "f"(b)); return r;
}
__device__ __forceinline__ void unpk(ull v, float& a, float& b) {
    asm("mov.b64 {%0,%1}, %2;" : "=f"(a), "=f"(b) : "l"(v));
}
__device__ __forceinline__ ull fma2(ull a, ull b, ull c) {
    ull d; asm("fma.rn.f32x2 %0, %1, %2, %3;" : "=l"(d) : "l"(a), "l"(b), "l"(c)); return d;
}
__device__ __forceinline__ ull mul2(ull a, ull b) {
    ull d; asm("mul.rn.f32x2 %0, %1, %2;" : "=l"(d) : "l"(a), "l"(b)); return d;
}
__device__ __forceinline__ ull relu2(ull v) {
    float a, b; unpk(v, a, b);
    return pk(fmaxf(a, 0.f), fmaxf(b, 0.f));
}
__device__ __forceinline__ ull shfl_add2(ull v, int off) {
    ull t = __shfl_xor_sync(0xFFFFFFFFu, v, off);
    float xa, xb, ya, yb;
    unpk(v, xa, xb); unpk(t, ya, yb);
    return pk(xa + ya, xb + yb);
}
__device__ __forceinline__ float4 shflx4(float4 v, int m) {
    float4 r;
    r.x = __shfl_xor_sync(0xFFFFFFFFu, v.x, m);
    r.y = __shfl_xor_sync(0xFFFFFFFFu, v.y, m);
    r.z = __shfl_xor_sync(0xFFFFFFFFu, v.z, m);
    r.w = __shfl_xor_sync(0xFFFFFFFFu, v.w, m);
    return r;
}

// ---------------------------------------------------------------- K1: 3 threads/point, axis-major PE
// blocks [0, PREP_BLOCKS): xp (64 points x 3 axes = 192 threads)
// blocks [PREP_BLOCKS, PREP_BLOCKS+DIR_BLOCKS): xd (64 rays x 3 axes)
__global__ __launch_bounds__(192) void k_prep(const float* __restrict__ pts,
                                              const float* __restrict__ dirs) {
    __shared__ __align__(16) float srow[64 * 68];   // xp: stride 68; xd: stride 36 view
    int b = blockIdx.x, t = threadIdx.x;
    int nl = t / 3, a = t - 3 * nl;

    if (b < PREP_BLOCKS) {
        int gid = b * 192 + t;
        int n = b * 64 + nl;
        float v = pts[gid];

        if (a == 0) {
            float y = pts[gid + 1];
            float z = pts[gid + 2];
            float sx = fminf(fmaxf(((v + 1.5f) / 3.0f) * 16.0f, 0.0f), 15.0f);
            float sy = fminf(fmaxf(((y + 1.5f) / 3.0f) * 16.0f, 0.0f), 15.0f);
            float sz = fminf(fmaxf(((z + 1.5f) / 3.0f) * 16.0f, 0.0f), 15.0f);
            int e = ((int)sx) * 256 + ((int)sy) * 16 + (int)sz;
            g_expert[n] = e;
            g_rank[n] = atomicAdd(&g_counts[e], 1);
        }

        // anchored double-angle chain for this axis: out[0..20] = [v, s0,c0,...,s9,c9]
        float out[21];
        out[0] = v;
        float s, c;
        sincosf(v, &s, &c);
        out[1] = s; out[2] = c;
        float sl = s, cl = c;
        #pragma unroll
        for (int f = 1; f < 5; f++) {
            float ns = 2.0f * sl * cl;
            float nc = (cl - sl) * (cl + sl);
            out[2 * f + 1] = ns; out[2 * f + 2] = nc;
            sl = ns; cl = nc;
        }
        sincosf(v * 32.0f, &s, &c);
        out[11] = s; out[12] = c;
        sl = s; cl = c;
        #pragma unroll
        for (int f = 6; f < 10; f++) {
            float ns = 2.0f * sl * cl;
            float nc = (cl - sl) * (cl + sl);
            out[2 * f + 1] = ns; out[2 * f + 2] = nc;
            sl = ns; cl = nc;
        }

        float* row = srow + nl * 68 + a * 21;
        #pragma unroll
        for (int r = 0; r < 21; r++) row[r] = out[r];
        if (a == 2) srow[nl * 68 + 63] = 0.f;
        __syncthreads();

        // coalesced float4 writeout (64 rows x 16 quads)
        for (int i = t; i < 1024; i += 192) {
            int p = i >> 4, q = i & 15;
            g_xp4[(size_t)b * 1024 + i] = *(const float4*)(srow + p * 68 + q * 4);
        }
    } else {
        int rb = b - PREP_BLOCKS;
        int gid = rb * 192 + t;
        float v = dirs[gid];

        float out[9];
        out[0] = v;
        float s, c;
        sincosf(v, &s, &c);
        out[1] = s; out[2] = c;
        float sl = s, cl = c;
        #pragma unroll
        for (int f = 1; f < 4; f++) {
            float ns = 2.0f * sl * cl;
            float nc = (cl - sl) * (cl + sl);
            out[2 * f + 1] = ns; out[2 * f + 2] = nc;
            sl = ns; cl = nc;
        }

        float* row = srow + nl * 36 + a * 9;
        #pragma unroll
        for (int r = 0; r < 9; r++) row[r] = out[r];
        if (a == 2) {
            #pragma unroll
            for (int k = 27; k < 32; k++) srow[nl * 36 + k] = 0.f;
        }
        __syncthreads();

        for (int i = t; i < 512; i += 192) {
            int p = i >> 3, q = i & 7;
            g_xd4[(size_t)rb * 512 + i] = *(const float4*)(srow + p * 36 + q * 4);
        }
    }
}

// ---------------------------------------------------------------- K2: oct scan (block 0) + scatter
__global__ void k_scan_scatter() {
    if (blockIdx.x == 0) {
        __shared__ int wsum[8];
        int tid = threadIdx.x;
        int base = tid * 16;
        int c[16], od[16];
        int local = 0;
        #pragma unroll
        for (int i = 0; i < 16; i++) {
            c[i] = g_counts[base + i];
            od[i] = (c[i] + 7) >> 3;
            local += od[i];
        }
        int lane = tid & 31, w = tid >> 5;
        int v = local;
        #pragma unroll
        for (int off = 1; off < 32; off <<= 1) {
            int t = __shfl_up_sync(0xFFFFFFFFu, v, off);
            if (lane >= off) v += t;
        }
        if (lane == 31) wsum[w] = v;
        __syncthreads();
        if (w == 0 && lane < 8) {
            int s = wsum[lane];
            #pragma unroll
            for (int off = 1; off < 8; off <<= 1) {
                int t = __shfl_up_sync(0xFFu, s, off);
                if (lane >= off) s += t;
            }
            wsum[lane] = s;
        }
        __syncthreads();
        int runo = v - local;
        if (w > 0) runo += wsum[w - 1];
        #pragma unroll
        for (int i = 0; i < 16; i++) {
            int poff = runo * 8;
            g_offsets[base + i] = poff;
            for (int j = 0; j < od[i]; j++) g_oexp[runo + j] = base + i;
            for (int s = c[i]; s < od[i] * 8; s++) g_olist[poff + s] = -1;
            runo += od[i];
        }
        if (tid == 255) g_O = runo;
        __threadfence();
        __syncthreads();
        if (tid == 0) atomicExch(&g_flag, 1);
    } else {
        int n = (blockIdx.x - 1) * 256 + threadIdx.x;
        int e = g_expert[n];
        int r = g_rank[n];
        if (threadIdx.x == 0) {
            while (atomicAdd(&g_flag, 0) == 0) { __nanosleep(64); }
        }
        __syncthreads();
        __threadfence();
        g_olist[g_offsets[e] + r] = n;
    }
}

// ---------------------------------------------------------------- K3: warp-autonomous, 8 pts/iter, f32x2, contiguous octs
__global__ __launch_bounds__(256, 2) void k_mlp(
    const float* __restrict__ W1, const float* __restrict__ b1,
    const float* __restrict__ W2, const float* __restrict__ b2,
    const float* __restrict__ Wf, const float* __restrict__ bf,
    const float* __restrict__ Wsig, const float* __restrict__ bsig,
    const float* __restrict__ Wv, const float* __restrict__ bv,
    const float* __restrict__ Wrgb, const float* __restrict__ brgb,
    float* __restrict__ out_rgb, float* __restrict__ out_sig)
{
    if (blockIdx.x == 0) {
        if (threadIdx.x == 0) g_flag = 0;
        for (int i = threadIdx.x; i < NEXP; i += 256) g_counts[i] = 0;
    }

    __shared__ __align__(16) float sAct[8][1024];
    int tid = threadIdx.x;
    int w = tid >> 5, lane = tid & 31;
    float* xpw = sAct[w];
    float* xdw = xpw + 512;
    ull*   shw = (ull*)(xpw + 768);

    int O = g_O;
    int NW = gridDim.x * 8;
    int wg = blockIdx.x * 8 + w;
    int q0 = (int)(((long long)wg * O) / NW);
    int q1 = (int)(((long long)(wg + 1) * O) / NW);

    for (int o = q0; o < q1; o++) {
        int e = g_oexp[o];
        int4 ra = ((const int4*)g_olist)[2 * o];
        int4 rb = ((const int4*)g_olist)[2 * o + 1];
        int n0 = ra.x;
        int n1 = (ra.y < 0) ? n0 : ra.y;
        int n2 = (ra.z < 0) ? n0 : ra.z;
        int n3 = (ra.w < 0) ? n0 : ra.w;
        int n4 = (rb.x < 0) ? n0 : rb.x;
        int n5 = (rb.y < 0) ? n0 : rb.y;
        int n6 = (rb.z < 0) ? n0 : rb.z;
        int n7 = (rb.w < 0) ? n0 : rb.w;

        const float* W1e = W1 + (size_t)e * 2016;
        const float* W2e = W2 + (size_t)e * 1024;
        const float* Wfe = Wf + (size_t)e * 1024;
        const float* Wve = Wv + (size_t)e * 1888;
        float bb1 = __ldg(b1 + (size_t)e * 32 + lane);
        float bb2 = __ldg(b2 + (size_t)e * 32 + lane);
        float bbf = __ldg(bf + (size_t)e * 32 + lane);
        float bbv = __ldg(bv + (size_t)e * 32 + lane);
        float wsg = __ldg(Wsig + (size_t)e * 32 + lane);
        float wr0 = __ldg(Wrgb + (size_t)e * 96 + lane * 3 + 0);
        float wr1 = __ldg(Wrgb + (size_t)e * 96 + lane * 3 + 1);
        float wr2 = __ldg(Wrgb + (size_t)e * 96 + lane * 3 + 2);

        // ---- stage xp pair-interleaved ----
        {
            int q = lane & 15;
            bool hi = (lane & 16) != 0;
            #pragma unroll
            for (int r = 0; r < 4; r++) {
                int ne = (r == 0) ? n0 : (r == 1) ? n2 : (r == 2) ? n4 : n6;
                int no = (r == 0) ? n1 : (r == 1) ? n3 : (r == 2) ? n5 : n7;
                int nsel = hi ? no : ne;
                float4 v = g_xp4[(size_t)nsel * 16 + q];
                float4 u = shflx4(v, 16);
                float4 outv;
                if (!hi) outv = make_float4(v.x, u.x, v.y, u.y);
                else     outv = make_float4(u.z, v.z, u.w, v.w);
                *(float4*)&xpw[r * 128 + q * 8 + (hi ? 4 : 0)] = outv;
            }
        }
        // ---- stage xd pair-interleaved ----
        {
            int q = lane & 7;
            int ps = (lane >> 3) & 3;
            bool odd = (ps & 1) != 0;
            #pragma unroll
            for (int r = 0; r < 2; r++) {
                int na = (r == 0) ? n0 : n4;
                int nb = (r == 0) ? n1 : n5;
                int nc = (r == 0) ? n2 : n6;
                int nd = (r == 0) ? n3 : n7;
                int nsel = (ps == 0) ? na : (ps == 1) ? nb : (ps == 2) ? nc : nd;
                float4 v = g_xd4[(size_t)(nsel >> 6) * 8 + q];
                float4 u = shflx4(v, 8);
                float4 outv;
                if (!odd) outv = make_float4(v.x, u.x, v.y, u.y);
                else      outv = make_float4(u.z, v.z, u.w, v.w);
                int pairIdx = 2 * r + (ps >> 1);
                *(float4*)&xdw[pairIdx * 64 + q * 8 + (odd ? 4 : 0)] = outv;
            }
        }
        __syncwarp();

        // ---- layer 1: 63 -> 32, relu (axis-major slots, permuted weight rows) ----
        ull a01 = pk(bb1, bb1), a23 = a01, a45 = a01, a67 = a01;
        #pragma unroll
        for (int i = 0; i < 62; i += 2) {
            float w0 = __ldg(W1e + oxp(i + 0) * 32 + lane);
            float w1 = __ldg(W1e + oxp(i + 1) * 32 + lane);
            ull d0 = pk(w0, w0), d1 = pk(w1, w1);
            ulonglong2 p0 = *(const ulonglong2*)&xpw[0 * 128 + 2 * i];
            ulonglong2 p1 = *(const ulonglong2*)&xpw[1 * 128 + 2 * i];
            ulonglong2 p2 = *(const ulonglong2*)&xpw[2 * 128 + 2 * i];
            ulonglong2 p3 = *(const ulonglong2*)&xpw[3 * 128 + 2 * i];
            a01 = fma2(p0.x, d0, a01); a01 = fma2(p0.y, d1, a01);
            a23 = fma2(p1.x, d0, a23); a23 = fma2(p1.y, d1, a23);
            a45 = fma2(p2.x, d0, a45); a45 = fma2(p2.y, d1, a45);
            a67 = fma2(p3.x, d0, a67); a67 = fma2(p3.y, d1, a67);
        }
        {   // slot 62
            float w0 = __ldg(W1e + oxp(62) * 32 + lane);
            ull d0 = pk(w0, w0);
            a01 = fma2(((const ull*)xpw)[0 * 64 + 62], d0, a01);
            a23 = fma2(((const ull*)xpw)[1 * 64 + 62], d0, a23);
            a45 = fma2(((const ull*)xpw)[2 * 64 + 62], d0, a45);
            a67 = fma2(((const ull*)xpw)[3 * 64 + 62], d0, a67);
        }
        a01 = relu2(a01); a23 = relu2(a23); a45 = relu2(a45); a67 = relu2(a67);
        shw[0 * 32 + lane] = a01; shw[1 * 32 + lane] = a23;
        shw[2 * 32 + lane] = a45; shw[3 * 32 + lane] = a67;
        __syncwarp();

        // ---- layer 2: 32 -> 32, relu ----
        ull g01 = pk(bb2, bb2), g23 = g01, g45 = g01, g67 = g01;
        #pragma unroll
        for (int i = 0; i < 32; i += 2) {
            float w0 = __ldg(W2e + (i + 0) * 32 + lane);
            float w1 = __ldg(W2e + (i + 1) * 32 + lane);
            ull d0 = pk(w0, w0), d1 = pk(w1, w1);
            ulonglong2 p0 = *(const ulonglong2*)&shw[0 * 32 + i];
            ulonglong2 p1 = *(const ulonglong2*)&shw[1 * 32 + i];
            ulonglong2 p2 = *(const ulonglong2*)&shw[2 * 32 + i];
            ulonglong2 p3 = *(const ulonglong2*)&shw[3 * 32 + i];
            g01 = fma2(p0.x, d0, g01); g01 = fma2(p0.y, d1, g01);
            g23 = fma2(p1.x, d0, g23); g23 = fma2(p1.y, d1, g23);
            g45 = fma2(p2.x, d0, g45); g45 = fma2(p2.y, d1, g45);
            g67 = fma2(p3.x, d0, g67); g67 = fma2(p3.y, d1, g67);
        }
        g01 = relu2(g01); g23 = relu2(g23); g45 = relu2(g45); g67 = relu2(g67);

        ull dwsg = pk(wsg, wsg);
        ull s01 = mul2(g01, dwsg), s23 = mul2(g23, dwsg);
        ull s45 = mul2(g45, dwsg), s67 = mul2(g67, dwsg);

        __syncwarp();
        shw[0 * 32 + lane] = g01; shw[1 * 32 + lane] = g23;
        shw[2 * 32 + lane] = g45; shw[3 * 32 + lane] = g67;
        __syncwarp();

        // ---- feature: 32 -> 32 (linear) ----
        ull f01 = pk(bbf, bbf), f23 = f01, f45 = f01, f67 = f01;
        #pragma unroll
        for (int i = 0; i < 32; i += 2) {
            float w0 = __ldg(Wfe + (i + 0) * 32 + lane);
            float w1 = __ldg(Wfe + (i + 1) * 32 + lane);
            ull d0 = pk(w0, w0), d1 = pk(w1, w1);
            ulonglong2 p0 = *(const ulonglong2*)&shw[0 * 32 + i];
            ulonglong2 p1 = *(const ulonglong2*)&shw[1 * 32 + i];
            ulonglong2 p2 = *(const ulonglong2*)&shw[2 * 32 + i];
            ulonglong2 p3 = *(const ulonglong2*)&shw[3 * 32 + i];
            f01 = fma2(p0.x, d0, f01); f01 = fma2(p0.y, d1, f01);
            f23 = fma2(p1.x, d0, f23); f23 = fma2(p1.y, d1, f23);
            f45 = fma2(p2.x, d0, f45); f45 = fma2(p2.y, d1, f45);
            f67 = fma2(p3.x, d0, f67); f67 = fma2(p3.y, d1, f67);
        }
        __syncwarp();
        shw[0 * 32 + lane] = f01; shw[1 * 32 + lane] = f23;
        shw[2 * 32 + lane] = f45; shw[3 * 32 + lane] = f67;
        __syncwarp();

        // ---- view layer: [feat(32), xd(27)] -> 32, relu ----
        ull v01 = pk(bbv, bbv), v23 = v01, v45 = v01, v67 = v01;
        #pragma unroll
        for (int i = 0; i < 32; i += 2) {
            float w0 = __ldg(Wve + (i + 0) * 32 + lane);
            float w1 = __ldg(Wve + (i + 1) * 32 + lane);
            ull d0 = pk(w0, w0), d1 = pk(w1, w1);
            ulonglong2 p0 = *(const ulonglong2*)&shw[0 * 32 + i];
            ulonglong2 p1 = *(const ulonglong2*)&shw[1 * 32 + i];
            ulonglong2 p2 = *(const ulonglong2*)&shw[2 * 32 + i];
            ulonglong2 p3 = *(const ulonglong2*)&shw[3 * 32 + i];
            v01 = fma2(p0.x, d0, v01); v01 = fma2(p0.y, d1, v01);
            v23 = fma2(p1.x, d0, v23); v23 = fma2(p1.y, d1, v23);
            v45 = fma2(p2.x, d0, v45); v45 = fma2(p2.y, d1, v45);
            v67 = fma2(p3.x, d0, v67); v67 = fma2(p3.y, d1, v67);
        }
        #pragma unroll
        for (int j = 0; j < 26; j += 2) {
            float w0 = __ldg(Wve + (HID + oxd(j + 0)) * 32 + lane);
            float w1 = __ldg(Wve + (HID + oxd(j + 1)) * 32 + lane);
            ull d0 = pk(w0, w0), d1 = pk(w1, w1);
            ulonglong2 p0 = *(const ulonglong2*)&xdw[0 * 64 + 2 * j];
            ulonglong2 p1 = *(const ulonglong2*)&xdw[1 * 64 + 2 * j];
            ulonglong2 p2 = *(const ulonglong2*)&xdw[2 * 64 + 2 * j];
            ulonglong2 p3 = *(const ulonglong2*)&xdw[3 * 64 + 2 * j];
            v01 = fma2(p0.x, d0, v01); v01 = fma2(p0.y, d1, v01);
            v23 = fma2(p1.x, d0, v23); v23 = fma2(p1.y, d1, v23);
            v45 = fma2(p2.x, d0, v45); v45 = fma2(p2.y, d1, v45);
            v67 = fma2(p3.x, d0, v67); v67 = fma2(p3.y, d1, v67);
        }
        {   // slot 26
            float w0 = __ldg(Wve + (HID + oxd(26)) * 32 + lane);
            ull d0 = pk(w0, w0);
            v01 = fma2(((const ull*)xdw)[0 * 32 + 26], d0, v01);
            v23 = fma2(((const ull*)xdw)[1 * 32 + 26], d0, v23);
            v45 = fma2(((const ull*)xdw)[2 * 32 + 26], d0, v45);
            v67 = fma2(((const ull*)xdw)[3 * 32 + 26], d0, v67);
        }
        v01 = relu2(v01); v23 = relu2(v23); v45 = relu2(v45); v67 = relu2(v67);

        ull dw0 = pk(wr0, wr0), dw1 = pk(wr1, wr1), dw2 = pk(wr2, wr2);
        ull r01x = mul2(v01, dw0), r01y = mul2(v01, dw1), r01z = mul2(v01, dw2);
        ull r23x = mul2(v23, dw0), r23y = mul2(v23, dw1), r23z = mul2(v23, dw2);
        ull r45x = mul2(v45, dw0), r45y = mul2(v45, dw1), r45z = mul2(v45, dw2);
        ull r67x = mul2(v67, dw0), r67y = mul2(v67, dw1), r67z = mul2(v67, dw2);

        #pragma unroll
        for (int off = 16; off > 0; off >>= 1) {
            s01  = shfl_add2(s01,  off);
            s23  = shfl_add2(s23,  off);
            s45  = shfl_add2(s45,  off);
            s67  = shfl_add2(s67,  off);
            r01x = shfl_add2(r01x, off);
            r01y = shfl_add2(r01y, off);
            r01z = shfl_add2(r01z, off);
            r23x = shfl_add2(r23x, off);
            r23y = shfl_add2(r23y, off);
            r23z = shfl_add2(r23z, off);
            r45x = shfl_add2(r45x, off);
            r45y = shfl_add2(r45y, off);
            r45z = shfl_add2(r45z, off);
            r67x = shfl_add2(r67x, off);
            r67y = shfl_add2(r67y, off);
            r67z = shfl_add2(r67z, off);
        }

        if (lane < 8) {
            int rawv = (lane == 0) ? ra.x : (lane == 1) ? ra.y : (lane == 2) ? ra.z : (lane == 3) ? ra.w
                     : (lane == 4) ? rb.x : (lane == 5) ? rb.y : (lane == 6) ? rb.z : rb.w;
            if (rawv >= 0) {
                int pr = lane >> 1;
                bool hi = (lane & 1) != 0;
                float lo_, hi_;
                ull sP = (pr == 0) ? s01 : (pr == 1) ? s23 : (pr == 2) ? s45 : s67;
                unpk(sP, lo_, hi_);  float sv = hi ? hi_ : lo_;
                ull xP = (pr == 0) ? r01x : (pr == 1) ? r23x : (pr == 2) ? r45x : r67x;
                unpk(xP, lo_, hi_);  float cx = hi ? hi_ : lo_;
                ull yP = (pr == 0) ? r01y : (pr == 1) ? r23y : (pr == 2) ? r45y : r67y;
                unpk(yP, lo_, hi_);  float cy = hi ? hi_ : lo_;
                ull zP = (pr == 0) ? r01z : (pr == 1) ? r23z : (pr == 2) ? r45z : r67z;
                unpk(zP, lo_, hi_);  float cz = hi ? hi_ : lo_;
                float bsg  = __ldg(bsig + e);
                float brc0 = __ldg(brgb + (size_t)e * 3 + 0);
                float brc1 = __ldg(brgb + (size_t)e * 3 + 1);
                float brc2 = __ldg(brgb + (size_t)e * 3 + 2);
                out_sig[rawv] = sv + bsg;
                out_rgb[(size_t)rawv * 3 + 0] = cx + brc0;
                out_rgb[(size_t)rawv * 3 + 1] = cy + brc1;
                out_rgb[(size_t)rawv * 3 + 2] = cz + brc2;
            }
        }
        __syncwarp();
    }
}

// ---------------------------------------------------------------- launch
extern "C" void kernel_launch(void* const* d_in, const int* in_sizes, int n_in,
                              void* d_out, int out_size) {
    const float* pts  = (const float*)d_in[0];
    const float* dirs = (const float*)d_in[1];
    const float* W1   = (const float*)d_in[2];
    const float* b1   = (const float*)d_in[3];
    const float* W2   = (const float*)d_in[4];
    const float* b2   = (const float*)d_in[5];
    const float* Wf   = (const float*)d_in[6];
    const float* bf   = (const float*)d_in[7];
    const float* Wsig = (const float*)d_in[8];
    const float* bsig = (const float*)d_in[9];
    const float* Wv   = (const float*)d_in[10];
    const float* bv   = (const float*)d_in[11];
    const float* Wrgb = (const float*)d_in[12];
    const float* brgb = (const float*)d_in[13];

    float* out_rgb = (float*)d_out;
    float* out_sig = (float*)d_out + (size_t)NPTS * 3;

    k_prep<<<PREP_BLOCKS + DIR_BLOCKS, 192>>>(pts, dirs);
    k_scan_scatter<<<257, 256>>>();
    k_mlp<<<GRID_MLP, 256>>>(W1, b1, W2, b2, Wf, bf, Wsig, bsig,
                             Wv, bv, Wrgb, brgb, out_rgb, out_sig);
}

// round 16
// speedup vs baseline: 1.0527x; 1.0527x over previous
#include <cuda_runtime.h>
#include <cstdint>
#include <math.h>

#define NEXP   4096
#define NPTS   65536
#define NRAYS  1024
#define HID    32
#define IN_PTS 63
#define IN_DIR 27
#define MAXO   14336
#define GRID_MLP 444
#define PREP_BLOCKS (NPTS / 64)    // 1024
#define DIR_BLOCKS  (NRAYS / 64)   // 16

typedef unsigned long long ull;

// ---- scratch (no allocations allowed) ----
__device__ int    g_counts[NEXP];
__device__ int    g_offsets[NEXP];       // point offsets, multiples of 8
__device__ int    g_expert[NPTS];
__device__ int    g_rank[NPTS];
__device__ int    g_flag;
__device__ int    g_O;                   // total octs
__device__ int    g_oexp[MAXO];          // oct -> expert
__device__ int    g_olist[MAXO * 8];     // padded point list (-1 = pad)
__device__ float4 g_xp4[NPTS * 16];      // FEATURE-MAJOR xp rows (63 pad 64)
__device__ float4 g_xd4[NRAYS * 8];      // FEATURE-MAJOR xd rows (27 pad 32)

// ---- f32x2 packed helpers ----
__device__ __forceinline__ ull pk(float a, float b) {
    ull r; asm("mov.b64 %0, {%1,%2};" : "=l"(r) : "f"(a), "f"(b)); return r;
}
__device__ __forceinline__ void unpk(ull v, float& a, float& b) {
    asm("mov.b64 {%0,%1}, %2;" : "=f"(a), "=f"(b) : "l"(v));
}
__device__ __forceinline__ ull fma2(ull a, ull b, ull c) {
    ull d; asm("fma.rn.f32x2 %0, %1, %2, %3;" : "=l"(d) : "l"(a), "l"(b), "l"(c)); return d;
}
__device__ __forceinline__ ull mul2(ull a, ull b) {
    ull d; asm("mul.rn.f32x2 %0, %1, %2;" : "=l"(d) : "l"(a), "l"(b)); return d;
}
__device__ __forceinline__ ull relu2(ull v) {
    float a, b; unpk(v, a, b);
    return pk(fmaxf(a, 0.f), fmaxf(b, 0.f));
}
__device__ __forceinline__ ull shfl_add2(ull v, int off) {
    ull t = __shfl_xor_sync(0xFFFFFFFFu, v, off);
    float xa, xb, ya, yb;
    unpk(v, xa, xb); unpk(t, ya, yb);
    return pk(xa + ya, xb + yb);
}
__device__ __forceinline__ float4 shflx4(float4 v, int m) {
    float4 r;
    r.x = __shfl_xor_sync(0xFFFFFFFFu, v.x, m);
    r.y = __shfl_xor_sync(0xFFFFFFFFu, v.y, m);
    r.z = __shfl_xor_sync(0xFFFFFFFFu, v.z, m);
    r.w = __shfl_xor_sync(0xFFFFFFFFu, v.w, m);
    return r;
}

// ---------------------------------------------------------------- K1: 3 threads/point, feature-major via smem scatter
__global__ __launch_bounds__(192) void k_prep(const float* __restrict__ pts,
                                              const float* __restrict__ dirs) {
    __shared__ __align__(16) float srow[64 * 68];
    int b = blockIdx.x, t = threadIdx.x;
    int nl = t / 3, a = t - 3 * nl;

    if (b < PREP_BLOCKS) {
        int gid = b * 192 + t;
        int n = b * 64 + nl;
        float v = pts[gid];

        if (a == 0) {
            float y = pts[gid + 1];
            float z = pts[gid + 2];
            float sx = fminf(fmaxf(((v + 1.5f) / 3.0f) * 16.0f, 0.0f), 15.0f);
            float sy = fminf(fmaxf(((y + 1.5f) / 3.0f) * 16.0f, 0.0f), 15.0f);
            float sz = fminf(fmaxf(((z + 1.5f) / 3.0f) * 16.0f, 0.0f), 15.0f);
            int e = ((int)sx) * 256 + ((int)sy) * 16 + (int)sz;
            g_expert[n] = e;
            g_rank[n] = atomicAdd(&g_counts[e], 1);
        }

        // anchored double-angle chain for this axis
        float out[21];
        out[0] = v;
        float s, c;
        sincosf(v, &s, &c);
        out[1] = s; out[2] = c;
        float sl = s, cl = c;
        #pragma unroll
        for (int f = 1; f < 5; f++) {
            float ns = 2.0f * sl * cl;
            float nc = (cl - sl) * (cl + sl);
            out[2 * f + 1] = ns; out[2 * f + 2] = nc;
            sl = ns; cl = nc;
        }
        sincosf(v * 32.0f, &s, &c);
        out[11] = s; out[12] = c;
        sl = s; cl = c;
        #pragma unroll
        for (int f = 6; f < 10; f++) {
            float ns = 2.0f * sl * cl;
            float nc = (cl - sl) * (cl + sl);
            out[2 * f + 1] = ns; out[2 * f + 2] = nc;
            sl = ns; cl = nc;
        }

        // scatter into FEATURE-MAJOR positions
        float* row = srow + nl * 68;
        row[a] = out[0];
        #pragma unroll
        for (int f = 0; f < 10; f++) {
            row[3 + 6 * f + a] = out[2 * f + 1];
            row[6 + 6 * f + a] = out[2 * f + 2];
        }
        if (a == 2) row[63] = 0.f;
        __syncthreads();

        for (int i = t; i < 1024; i += 192) {
            int p = i >> 4, q = i & 15;
            g_xp4[(size_t)b * 1024 + i] = *(const float4*)(srow + p * 68 + q * 4);
        }
    } else {
        int rb = b - PREP_BLOCKS;
        int gid = rb * 192 + t;
        float v = dirs[gid];

        float out[9];
        out[0] = v;
        float s, c;
        sincosf(v, &s, &c);
        out[1] = s; out[2] = c;
        float sl = s, cl = c;
        #pragma unroll
        for (int f = 1; f < 4; f++) {
            float ns = 2.0f * sl * cl;
            float nc = (cl - sl) * (cl + sl);
            out[2 * f + 1] = ns; out[2 * f + 2] = nc;
            sl = ns; cl = nc;
        }

        float* row = srow + nl * 36;
        row[a] = out[0];
        #pragma unroll
        for (int f = 0; f < 4; f++) {
            row[3 + 6 * f + a] = out[2 * f + 1];
            row[6 + 6 * f + a] = out[2 * f + 2];
        }
        if (a == 2) {
            #pragma unroll
            for (int k = 27; k < 32; k++) row[k] = 0.f;
        }
        __syncthreads();

        for (int i = t; i < 512; i += 192) {
            int p = i >> 3, q = i & 7;
            g_xd4[(size_t)rb * 512 + i] = *(const float4*)(srow + p * 36 + q * 4);
        }
    }
}

// ---------------------------------------------------------------- K2: oct scan (block 0) + scatter
__global__ void k_scan_scatter() {
    if (blockIdx.x == 0) {
        __shared__ int wsum[8];
        int tid = threadIdx.x;
        int base = tid * 16;
        int c[16], od[16];
        int local = 0;
        #pragma unroll
        for (int i = 0; i < 16; i++) {
            c[i] = g_counts[base + i];
            od[i] = (c[i] + 7) >> 3;
            local += od[i];
        }
        int lane = tid & 31, w = tid >> 5;
        int v = local;
        #pragma unroll
        for (int off = 1; off < 32; off <<= 1) {
            int t = __shfl_up_sync(0xFFFFFFFFu, v, off);
            if (lane >= off) v += t;
        }
        if (lane == 31) wsum[w] = v;
        __syncthreads();
        if (w == 0 && lane < 8) {
            int s = wsum[lane];
            #pragma unroll
            for (int off = 1; off < 8; off <<= 1) {
                int t = __shfl_up_sync(0xFFu, s, off);
                if (lane >= off) s += t;
            }
            wsum[lane] = s;
        }
        __syncthreads();
        int runo = v - local;
        if (w > 0) runo += wsum[w - 1];
        #pragma unroll
        for (int i = 0; i < 16; i++) {
            int poff = runo * 8;
            g_offsets[base + i] = poff;
            for (int j = 0; j < od[i]; j++) g_oexp[runo + j] = base + i;
            for (int s = c[i]; s < od[i] * 8; s++) g_olist[poff + s] = -1;
            runo += od[i];
        }
        if (tid == 255) g_O = runo;
        __threadfence();
        __syncthreads();
        if (tid == 0) atomicExch(&g_flag, 1);
    } else {
        int n = (blockIdx.x - 1) * 256 + threadIdx.x;
        int e = g_expert[n];
        int r = g_rank[n];
        if (threadIdx.x == 0) {
            while (atomicAdd(&g_flag, 0) == 0) { __nanosleep(64); }
        }
        __syncthreads();
        __threadfence();
        g_olist[g_offsets[e] + r] = n;
    }
}

// ---------------------------------------------------------------- K3: warp-autonomous, 8 pts/iter, f32x2, strided octs, occ 3
__global__ __launch_bounds__(256, 3) void k_mlp(
    const float* __restrict__ W1, const float* __restrict__ b1,
    const float* __restrict__ W2, const float* __restrict__ b2,
    const float* __restrict__ Wf, const float* __restrict__ bf,
    const float* __restrict__ Wsig, const float* __restrict__ bsig,
    const float* __restrict__ Wv, const float* __restrict__ bv,
    const float* __restrict__ Wrgb, const float* __restrict__ brgb,
    float* __restrict__ out_rgb, float* __restrict__ out_sig)
{
    if (blockIdx.x == 0) {
        if (threadIdx.x == 0) g_flag = 0;
        for (int i = threadIdx.x; i < NEXP; i += 256) g_counts[i] = 0;
    }

    __shared__ __align__(16) float sAct[8][1024];
    int tid = threadIdx.x;
    int w = tid >> 5, lane = tid & 31;
    float* xpw = sAct[w];
    float* xdw = xpw + 512;
    ull*   shw = (ull*)(xpw + 768);

    int O = g_O;
    int NW = gridDim.x * 8;
    int gw = blockIdx.x * 8 + w;

    for (int o = gw; o < O; o += NW) {
        int e = g_oexp[o];
        int4 ra = ((const int4*)g_olist)[2 * o];
        int4 rb = ((const int4*)g_olist)[2 * o + 1];
        int n0 = ra.x;
        int n1 = (ra.y < 0) ? n0 : ra.y;
        int n2 = (ra.z < 0) ? n0 : ra.z;
        int n3 = (ra.w < 0) ? n0 : ra.w;
        int n4 = (rb.x < 0) ? n0 : rb.x;
        int n5 = (rb.y < 0) ? n0 : rb.y;
        int n6 = (rb.z < 0) ? n0 : rb.z;
        int n7 = (rb.w < 0) ? n0 : rb.w;

        const float* W1e = W1 + (size_t)e * 2016;
        const float* W2e = W2 + (size_t)e * 1024;
        const float* Wfe = Wf + (size_t)e * 1024;
        const float* Wve = Wv + (size_t)e * 1888;
        float bb1 = __ldg(b1 + (size_t)e * 32 + lane);
        float bb2 = __ldg(b2 + (size_t)e * 32 + lane);
        float bbf = __ldg(bf + (size_t)e * 32 + lane);
        float bbv = __ldg(bv + (size_t)e * 32 + lane);
        float wsg = __ldg(Wsig + (size_t)e * 32 + lane);
        float wr0 = __ldg(Wrgb + (size_t)e * 96 + lane * 3 + 0);
        float wr1 = __ldg(Wrgb + (size_t)e * 96 + lane * 3 + 1);
        float wr2 = __ldg(Wrgb + (size_t)e * 96 + lane * 3 + 2);

        // ---- stage xp pair-interleaved ----
        {
            int q = lane & 15;
            bool hi = (lane & 16) != 0;
            #pragma unroll
            for (int r = 0; r < 4; r++) {
                int ne = (r == 0) ? n0 : (r == 1) ? n2 : (r == 2) ? n4 : n6;
                int no = (r == 0) ? n1 : (r == 1) ? n3 : (r == 2) ? n5 : n7;
                int nsel = hi ? no : ne;
                float4 v = g_xp4[(size_t)nsel * 16 + q];
                float4 u = shflx4(v, 16);
                float4 outv;
                if (!hi) outv = make_float4(v.x, u.x, v.y, u.y);
                else     outv = make_float4(u.z, v.z, u.w, v.w);
                *(float4*)&xpw[r * 128 + q * 8 + (hi ? 4 : 0)] = outv;
            }
        }
        // ---- stage xd pair-interleaved ----
        {
            int q = lane & 7;
            int ps = (lane >> 3) & 3;
            bool odd = (ps & 1) != 0;
            #pragma unroll
            for (int r = 0; r < 2; r++) {
                int na = (r == 0) ? n0 : n4;
                int nb = (r == 0) ? n1 : n5;
                int nc = (r == 0) ? n2 : n6;
                int nd = (r == 0) ? n3 : n7;
                int nsel = (ps == 0) ? na : (ps == 1) ? nb : (ps == 2) ? nc : nd;
                float4 v = g_xd4[(size_t)(nsel >> 6) * 8 + q];
                float4 u = shflx4(v, 8);
                float4 outv;
                if (!odd) outv = make_float4(v.x, u.x, v.y, u.y);
                else      outv = make_float4(u.z, v.z, u.w, v.w);
                int pairIdx = 2 * r + (ps >> 1);
                *(float4*)&xdw[pairIdx * 64 + q * 8 + (odd ? 4 : 0)] = outv;
            }
        }
        __syncwarp();

        // ---- layer 1: 63 -> 32, relu ----
        ull a01 = pk(bb1, bb1), a23 = a01, a45 = a01, a67 = a01;
        #pragma unroll
        for (int i = 0; i < 62; i += 2) {
            float w0 = __ldg(W1e + (i + 0) * 32 + lane);
            float w1 = __ldg(W1e + (i + 1) * 32 + lane);
            ull d0 = pk(w0, w0), d1 = pk(w1, w1);
            ulonglong2 p0 = *(const ulonglong2*)&xpw[0 * 128 + 2 * i];
            ulonglong2 p1 = *(const ulonglong2*)&xpw[1 * 128 + 2 * i];
            ulonglong2 p2 = *(const ulonglong2*)&xpw[2 * 128 + 2 * i];
            ulonglong2 p3 = *(const ulonglong2*)&xpw[3 * 128 + 2 * i];
            a01 = fma2(p0.x, d0, a01); a01 = fma2(p0.y, d1, a01);
            a23 = fma2(p1.x, d0, a23); a23 = fma2(p1.y, d1, a23);
            a45 = fma2(p2.x, d0, a45); a45 = fma2(p2.y, d1, a45);
            a67 = fma2(p3.x, d0, a67); a67 = fma2(p3.y, d1, a67);
        }
        {   // i = 62
            float w0 = __ldg(W1e + 62 * 32 + lane);
            ull d0 = pk(w0, w0);
            a01 = fma2(((const ull*)xpw)[0 * 64 + 62], d0, a01);
            a23 = fma2(((const ull*)xpw)[1 * 64 + 62], d0, a23);
            a45 = fma2(((const ull*)xpw)[2 * 64 + 62], d0, a45);
            a67 = fma2(((const ull*)xpw)[3 * 64 + 62], d0, a67);
        }
        a01 = relu2(a01); a23 = relu2(a23); a45 = relu2(a45); a67 = relu2(a67);
        shw[0 * 32 + lane] = a01; shw[1 * 32 + lane] = a23;
        shw[2 * 32 + lane] = a45; shw[3 * 32 + lane] = a67;
        __syncwarp();

        // ---- layer 2: 32 -> 32, relu ----
        ull g01 = pk(bb2, bb2), g23 = g01, g45 = g01, g67 = g01;
        #pragma unroll
        for (int i = 0; i < 32; i += 2) {
            float w0 = __ldg(W2e + (i + 0) * 32 + lane);
            float w1 = __ldg(W2e + (i + 1) * 32 + lane);
            ull d0 = pk(w0, w0), d1 = pk(w1, w1);
            ulonglong2 p0 = *(const ulonglong2*)&shw[0 * 32 + i];
            ulonglong2 p1 = *(const ulonglong2*)&shw[1 * 32 + i];
            ulonglong2 p2 = *(const ulonglong2*)&shw[2 * 32 + i];
            ulonglong2 p3 = *(const ulonglong2*)&shw[3 * 32 + i];
            g01 = fma2(p0.x, d0, g01); g01 = fma2(p0.y, d1, g01);
            g23 = fma2(p1.x, d0, g23); g23 = fma2(p1.y, d1, g23);
            g45 = fma2(p2.x, d0, g45); g45 = fma2(p2.y, d1, g45);
            g67 = fma2(p3.x, d0, g67); g67 = fma2(p3.y, d1, g67);
        }
        g01 = relu2(g01); g23 = relu2(g23); g45 = relu2(g45); g67 = relu2(g67);

        ull dwsg = pk(wsg, wsg);
        ull s01 = mul2(g01, dwsg), s23 = mul2(g23, dwsg);
        ull s45 = mul2(g45, dwsg), s67 = mul2(g67, dwsg);

        __syncwarp();
        shw[0 * 32 + lane] = g01; shw[1 * 32 + lane] = g23;
        shw[2 * 32 + lane] = g45; shw[3 * 32 + lane] = g67;
        __syncwarp();

        // ---- feature: 32 -> 32 (linear) ----
        ull f01 = pk(bbf, bbf), f23 = f01, f45 = f01, f67 = f01;
        #pragma unroll
        for (int i = 0; i < 32; i += 2) {
            float w0 = __ldg(Wfe + (i + 0) * 32 + lane);
            float w1 = __ldg(Wfe + (i + 1) * 32 + lane);
            ull d0 = pk(w0, w0), d1 = pk(w1, w1);
            ulonglong2 p0 = *(const ulonglong2*)&shw[0 * 32 + i];
            ulonglong2 p1 = *(const ulonglong2*)&shw[1 * 32 + i];
            ulonglong2 p2 = *(const ulonglong2*)&shw[2 * 32 + i];
            ulonglong2 p3 = *(const ulonglong2*)&shw[3 * 32 + i];
            f01 = fma2(p0.x, d0, f01); f01 = fma2(p0.y, d1, f01);
            f23 = fma2(p1.x, d0, f23); f23 = fma2(p1.y, d1, f23);
            f45 = fma2(p2.x, d0, f45); f45 = fma2(p2.y, d1, f45);
            f67 = fma2(p3.x, d0, f67); f67 = fma2(p3.y, d1, f67);
        }
        __syncwarp();
        shw[0 * 32 + lane] = f01; shw[1 * 32 + lane] = f23;
        shw[2 * 32 + lane] = f45; shw[3 * 32 + lane] = f67;
        __syncwarp();

        // ---- view layer: [feat(32), xd(27)] -> 32, relu ----
        ull v01 = pk(bbv, bbv), v23 = v01, v45 = v01, v67 = v01;
        #pragma unroll
        for (int i = 0; i < 32; i += 2) {
            float w0 = __ldg(Wve + (i + 0) * 32 + lane);
            float w1 = __ldg(Wve + (i + 1) * 32 + lane);
            ull d0 = pk(w0, w0), d1 = pk(w1, w1);
            ulonglong2 p0 = *(const ulonglong2*)&shw[0 * 32 + i];
            ulonglong2 p1 = *(const ulonglong2*)&shw[1 * 32 + i];
            ulonglong2 p2 = *(const ulonglong2*)&shw[2 * 32 + i];
            ulonglong2 p3 = *(const ulonglong2*)&shw[3 * 32 + i];
            v01 = fma2(p0.x, d0, v01); v01 = fma2(p0.y, d1, v01);
            v23 = fma2(p1.x, d0, v23); v23 = fma2(p1.y, d1, v23);
            v45 = fma2(p2.x, d0, v45); v45 = fma2(p2.y, d1, v45);
            v67 = fma2(p3.x, d0, v67); v67 = fma2(p3.y, d1, v67);
        }
        #pragma unroll
        for (int j = 0; j < 26; j += 2) {
            float w0 = __ldg(Wve + (HID + j + 0) * 32 + lane);
            float w1 = __ldg(Wve + (HID + j + 1) * 32 + lane);
            ull d0 = pk(w0, w0), d1 = pk(w1, w1);
            ulonglong2 p0 = *(const ulonglong2*)&xdw[0 * 64 + 2 * j];
            ulonglong2 p1 = *(const ulonglong2*)&xdw[1 * 64 + 2 * j];
            ulonglong2 p2 = *(const ulonglong2*)&xdw[2 * 64 + 2 * j];
            ulonglong2 p3 = *(const ulonglong2*)&xdw[3 * 64 + 2 * j];
            v01 = fma2(p0.x, d0, v01); v01 = fma2(p0.y, d1, v01);
            v23 = fma2(p1.x, d0, v23); v23 = fma2(p1.y, d1, v23);
            v45 = fma2(p2.x, d0, v45); v45 = fma2(p2.y, d1, v45);
            v67 = fma2(p3.x, d0, v67); v67 = fma2(p3.y, d1, v67);
        }
        {   // j = 26
            float w0 = __ldg(Wve + (HID + 26) * 32 + lane);
            ull d0 = pk(w0, w0);
            v01 = fma2(((const ull*)xdw)[0 * 32 + 26], d0, v01);
            v23 = fma2(((const ull*)xdw)[1 * 32 + 26], d0, v23);
            v45 = fma2(((const ull*)xdw)[2 * 32 + 26], d0, v45);
            v67 = fma2(((const ull*)xdw)[3 * 32 + 26], d0, v67);
        }
        v01 = relu2(v01); v23 = relu2(v23); v45 = relu2(v45); v67 = relu2(v67);

        ull dw0 = pk(wr0, wr0), dw1 = pk(wr1, wr1), dw2 = pk(wr2, wr2);
        ull r01x = mul2(v01, dw0), r01y = mul2(v01, dw1), r01z = mul2(v01, dw2);
        ull r23x = mul2(v23, dw0), r23y = mul2(v23, dw1), r23z = mul2(v23, dw2);
        ull r45x = mul2(v45, dw0), r45y = mul2(v45, dw1), r45z = mul2(v45, dw2);
        ull r67x = mul2(v67, dw0), r67y = mul2(v67, dw1), r67z = mul2(v67, dw2);

        #pragma unroll
        for (int off = 16; off > 0; off >>= 1) {
            s01  = shfl_add2(s01,  off);
            s23  = shfl_add2(s23,  off);
            s45  = shfl_add2(s45,  off);
            s67  = shfl_add2(s67,  off);
            r01x = shfl_add2(r01x, off);
            r01y = shfl_add2(r01y, off);
            r01z = shfl_add2(r01z, off);
            r23x = shfl_add2(r23x, off);
            r23y = shfl_add2(r23y, off);
            r23z = shfl_add2(r23z, off);
            r45x = shfl_add2(r45x, off);
            r45y = shfl_add2(r45y, off);
            r45z = shfl_add2(r45z, off);
            r67x = shfl_add2(r67x, off);
            r67y = shfl_add2(r67y, off);
            r67z = shfl_add2(r67z, off);
        }

        if (lane < 8) {
            int rawv = (lane == 0) ? ra.x : (lane == 1) ? ra.y : (lane == 2) ? ra.z : (lane == 3) ? ra.w
                     : (lane == 4) ? rb.x : (lane == 5) ? rb.y : (lane == 6) ? rb.z : rb.w;
            if (rawv >= 0) {
                int pr = lane >> 1;
                bool hi = (lane & 1) != 0;
                float lo_, hi_;
                ull sP = (pr == 0) ? s01 : (pr == 1) ? s23 : (pr == 2) ? s45 : s67;
                unpk(sP, lo_, hi_);  float sv = hi ? hi_ : lo_;
                ull xP = (pr == 0) ? r01x : (pr == 1) ? r23x : (pr == 2) ? r45x : r67x;
                unpk(xP, lo_, hi_);  float cx = hi ? hi_ : lo_;
                ull yP = (pr == 0) ? r01y : (pr == 1) ? r23y : (pr == 2) ? r45y : r67y;
                unpk(yP, lo_, hi_);  float cy = hi ? hi_ : lo_;
                ull zP = (pr == 0) ? r01z : (pr == 1) ? r23z : (pr == 2) ? r45z : r67z;
                unpk(zP, lo_, hi_);  float cz = hi ? hi_ : lo_;
                float bsg  = __ldg(bsig + e);
                float brc0 = __ldg(brgb + (size_t)e * 3 + 0);
                float brc1 = __ldg(brgb + (size_t)e * 3 + 1);
                float brc2 = __ldg(brgb + (size_t)e * 3 + 2);
                out_sig[rawv] = sv + bsg;
                out_rgb[(size_t)rawv * 3 + 0] = cx + brc0;
                out_rgb[(size_t)rawv * 3 + 1] = cy + brc1;
                out_rgb[(size_t)rawv * 3 + 2] = cz + brc2;
            }
        }
        __syncwarp();
    }
}

// ---------------------------------------------------------------- launch
extern "C" void kernel_launch(void* const* d_in, const int* in_sizes, int n_in,
                              void* d_out, int out_size) {
    const float* pts  = (const float*)d_in[0];
    const float* dirs = (const float*)d_in[1];
    const float* W1   = (const float*)d_in[2];
    const float* b1   = (const float*)d_in[3];
    const float* W2   = (const float*)d_in[4];
    const float* b2   = (const float*)d_in[5];
    const float* Wf   = (const float*)d_in[6];
    const float* bf   = (const float*)d_in[7];
    const float* Wsig = (const float*)d_in[8];
    const float* bsig = (const float*)d_in[9];
    const float* Wv   = (const float*)d_in[10];
    const float* bv   = (const float*)d_in[11];
    const float* Wrgb = (const float*)d_in[12];
    const float* brgb = (const float*)d_in[13];

    float* out_rgb = (float*)d_out;
    float* out_sig = (float*)d_out + (size_t)NPTS * 3;

    k_prep<<<PREP_BLOCKS + DIR_BLOCKS, 192>>>(pts, dirs);
    k_scan_scatter<<<257, 256>>>();
    k_mlp<<<GRID_MLP, 256>>>(W1, b1, W2, b2, Wf, bf, Wsig, bsig,
                             Wv, bv, Wrgb, brgb, out_rgb, out_sig);
}